// round 8
// baseline (speedup 1.0000x reference)
#include <cuda_runtime.h>

// Batched Kalman filter + forecast. B=16384 rows, T=504 (336 filter + 168 fcst).
// 256 blocks x 32 threads (1 warp), 2 rows per thread -> two independent
// recurrences interleaved for ILP (the serial FMA/RCP chain is the bottleneck).
// 24-step tiles, PIPE=3 cp.async pipeline with issue-at-top (2-period lead).
// Output staging overlays the dead T_obs slots of pipe stages 0/1 (forecast
// phase loads skip T_obs). smem row stride 28 floats -> conflict-free LDS.128.
// P_update = (1-K)^2*Pp + K^2*R == K*R exactly (K = Pp/S, 1-K = R/S).

#define TTOT   504
#define LHIST  336
#define HFCST  168
#define TILE   24
#define NTILES 21     // 504/24
#define FTILES 14     // 336/24
#define RPB    64     // rows per block
#define NTHR   32     // threads per block (one warp); 2 rows per thread
#define SROW   28     // smem floats per row (24 data + 4 pad; 7 x 16B groups)
#define SARR   (RPB*SROW)              // 1792 floats per array per stage
#define PIPE   3
#define CHK    6                       // 16B chunks per row per tile
#define SIN_FLOATS  (PIPE*5*SARR)      // 26880
#define SMEM_BYTES  (SIN_FLOATS*4)     // 107520 B -> 2 blocks/SM

#define EL(v,i) ((i)==0?(v).x:((i)==1?(v).y:((i)==2?(v).z:(v).w)))

__global__ __launch_bounds__(NTHR)
void kf_kernel(const float* __restrict__ T_obs,
               const float* __restrict__ T_air,
               const float* __restrict__ wind,
               const float* __restrict__ par,
               const float* __restrict__ dtv,
               const float* __restrict__ k_raw_p,
               const float* __restrict__ log_q_p,
               const float* __restrict__ log_r_p,
               const float* __restrict__ log_p0_p,
               const float* __restrict__ log_qs_p,
               const float* __restrict__ tpl_p,
               const float* __restrict__ tpq_p,
               const float* __restrict__ twc_p,
               const float* __restrict__ ts_p,
               const float* __restrict__ tfc_p,
               float* __restrict__ out,
               int B)
{
    extern __shared__ float smem[];
    float* sin   = smem;                        // [PIPE][5][SARR]
    float* soutT = sin + (0*5 + 0)*SARR;        // overlay: stage0 T_obs slot
    float* soutV = sin + (1*5 + 0)*SARR;        // overlay: stage1 T_obs slot

    const int tid  = threadIdx.x;
    const int row0 = blockIdx.x * RPB;

    const float* arrs[5] = {T_obs, T_air, wind, par, dtv};

    // cooperative coalesced tile loader; a0=1 skips T_obs (forecast tiles)
    auto issue_tile = [&](int tile, int buf, int a0) {
        for (int a = a0; a < 5; a++) {
            const float* gb = arrs[a];
            #pragma unroll
            for (int it = 0; it < 12; it++) {          // 64 rows * 6 chunks / 32 thr
                int q = tid + it * NTHR;               // 0..383
                int r = q / CHK, j = q - r * CHK;      // row, 16B chunk
                const float* g = gb + (size_t)(row0 + r) * TTOT + tile * TILE + j * 4;
                float* ds = sin + (buf * 5 + a) * SARR + r * SROW + j * 4;
                unsigned du = (unsigned)__cvta_generic_to_shared(ds);
                asm volatile("cp.async.cg.shared.global [%0], [%1], 16;\n" :: "r"(du), "l"(g));
            }
        }
        asm volatile("cp.async.commit_group;\n");
    };

    // prologue: issue tiles 0 and 1 (stages 0,1); scalar math overlaps
    issue_tile(0, 0, 0);
    issue_tile(1, 1, 0);

    const float k   = log1pf(expf(__ldg(k_raw_p)));
    const float qq  = expf(__ldg(log_qs_p)) * expf(__ldg(log_q_p));
    const float R   = expf(__ldg(log_r_p));
    const float P0  = expf(__ldg(log_p0_p));
    const float tpl = __ldg(tpl_p);
    const float tpq = __ldg(tpq_p);
    const float twc = __ldg(twc_p);
    const float ts  = __ldg(ts_p);
    const float tfc = __ldg(tfc_p);

    // two independent row states per thread (rows tid and tid+32)
    float sA = 0.0f, PA = P0, pTaA = 0.0f, pwA = 0.0f, ppA = 0.0f;
    float sB = 0.0f, PB = P0, pTaB = 0.0f, pwB = 0.0f, ppB = 0.0f;

    for (int tile = 0; tile < NTILES; ++tile) {
        const int buf = tile % PIPE;
        asm volatile("cp.async.wait_group %0;\n" :: "n"(PIPE - 2) : "memory");
        __syncwarp();
        // issue tile+2 into buf (tile+2)%PIPE == (tile-1)%PIPE (freed last iter)
        if (tile + PIPE - 1 < NTILES)
            issue_tile(tile + PIPE - 1, (tile + PIPE - 1) % PIPE,
                       (tile + PIPE - 1 >= FTILES) ? 1 : 0);

        const float* base = sin + buf * 5 * SARR;
        const float* byA  = base + tid * SROW;
        const float* byB  = base + (tid + NTHR) * SROW;

        if (tile < FTILES) {
            // ---------------- filter phase ----------------
            #pragma unroll
            for (int g = 0; g < CHK; g++) {
                float4 yA = *(const float4*)(byA + 0*SARR + g*4);
                float4 tA = *(const float4*)(byA + 1*SARR + g*4);
                float4 wA = *(const float4*)(byA + 2*SARR + g*4);
                float4 pA = *(const float4*)(byA + 3*SARR + g*4);
                float4 dA = *(const float4*)(byA + 4*SARR + g*4);
                float4 yB = *(const float4*)(byB + 0*SARR + g*4);
                float4 tB = *(const float4*)(byB + 1*SARR + g*4);
                float4 wB = *(const float4*)(byB + 2*SARR + g*4);
                float4 pB = *(const float4*)(byB + 3*SARR + g*4);
                float4 dB = *(const float4*)(byB + 4*SARR + g*4);
                #pragma unroll
                for (int i = 0; i < 4; i++) {
                    if (!(tile == 0 && g == 0 && i == 0)) {
                        // row A
                        {
                            float dtt = fmaxf(EL(dA,i), 1.0f);
                            float dT  = sA - pTaA;
                            float cl  = tpl * ppA + tpq * ppA * ppA + twc * pwA
                                      + ts * dT + tfc * pwA * dT;
                            float Tp  = sA + (cl - k * dT) * dtt;
                            Tp = fminf(fmaxf(Tp, -50.0f), 100.0f);
                            float F = 1.0f + ((ts + tfc * pwA) - k) * dtt;
                            F = fminf(fmaxf(F, -2.0f), 2.0f);
                            float Pp = F * F * PA + qq * dtt;
                            Pp = fminf(fmaxf(Pp, 1e-10f), 1e6f);
                            float K = __fdividef(Pp, Pp + R);
                            sA = Tp + K * (EL(yA,i) - Tp);
                            PA = K * R;
                        }
                        // row B
                        {
                            float dtt = fmaxf(EL(dB,i), 1.0f);
                            float dT  = sB - pTaB;
                            float cl  = tpl * ppB + tpq * ppB * ppB + twc * pwB
                                      + ts * dT + tfc * pwB * dT;
                            float Tp  = sB + (cl - k * dT) * dtt;
                            Tp = fminf(fmaxf(Tp, -50.0f), 100.0f);
                            float F = 1.0f + ((ts + tfc * pwB) - k) * dtt;
                            F = fminf(fmaxf(F, -2.0f), 2.0f);
                            float Pp = F * F * PB + qq * dtt;
                            Pp = fminf(fmaxf(Pp, 1e-10f), 1e6f);
                            float K = __fdividef(Pp, Pp + R);
                            sB = Tp + K * (EL(yB,i) - Tp);
                            PB = K * R;
                        }
                    } else {
                        sA = EL(yA,i);
                        sB = EL(yB,i);
                    }
                    pTaA = EL(tA,i); pwA = EL(wA,i); ppA = EL(pA,i);
                    pTaB = EL(tB,i); pwB = EL(wB,i); ppB = EL(pB,i);
                }
            }
            __syncwarp();                  // reads of buf done before refill
        } else {
            // ---------------- forecast phase ----------------
            #pragma unroll
            for (int g = 0; g < CHK; g++) {
                float4 tA = *(const float4*)(byA + 1*SARR + g*4);
                float4 wA = *(const float4*)(byA + 2*SARR + g*4);
                float4 pA = *(const float4*)(byA + 3*SARR + g*4);
                float4 dA = *(const float4*)(byA + 4*SARR + g*4);
                float4 tB = *(const float4*)(byB + 1*SARR + g*4);
                float4 wB = *(const float4*)(byB + 2*SARR + g*4);
                float4 pB = *(const float4*)(byB + 3*SARR + g*4);
                float4 dB = *(const float4*)(byB + 4*SARR + g*4);
                float oTA[4], oVA[4], oTB[4], oVB[4];
                #pragma unroll
                for (int i = 0; i < 4; i++) {
                    {
                        float dtt = fmaxf(EL(dA,i), 1.0f);
                        float dT  = sA - pTaA;
                        float cl  = tpl * ppA + tpq * ppA * ppA + twc * pwA
                                  + ts * dT + tfc * pwA * dT;
                        float Tp  = sA + (cl - k * dT) * dtt;
                        Tp = fminf(fmaxf(Tp, -50.0f), 100.0f);
                        float F = 1.0f + ((ts + tfc * pwA) - k) * dtt;
                        F = fminf(fmaxf(F, -2.0f), 2.0f);
                        float Pp = F * F * PA + qq * dtt;
                        Pp = fminf(fmaxf(Pp, 1e-10f), 1e6f);
                        sA = Tp; PA = Pp; oTA[i] = Tp; oVA[i] = Pp;
                        pTaA = EL(tA,i); pwA = EL(wA,i); ppA = EL(pA,i);
                    }
                    {
                        float dtt = fmaxf(EL(dB,i), 1.0f);
                        float dT  = sB - pTaB;
                        float cl  = tpl * ppB + tpq * ppB * ppB + twc * pwB
                                  + ts * dT + tfc * pwB * dT;
                        float Tp  = sB + (cl - k * dT) * dtt;
                        Tp = fminf(fmaxf(Tp, -50.0f), 100.0f);
                        float F = 1.0f + ((ts + tfc * pwB) - k) * dtt;
                        F = fminf(fmaxf(F, -2.0f), 2.0f);
                        float Pp = F * F * PB + qq * dtt;
                        Pp = fminf(fmaxf(Pp, 1e-10f), 1e6f);
                        sB = Tp; PB = Pp; oTB[i] = Tp; oVB[i] = Pp;
                        pTaB = EL(tB,i); pwB = EL(wB,i); ppB = EL(pB,i);
                    }
                }
                *(float4*)(soutT + tid * SROW + g*4)          = make_float4(oTA[0],oTA[1],oTA[2],oTA[3]);
                *(float4*)(soutT + (tid+NTHR) * SROW + g*4)   = make_float4(oTB[0],oTB[1],oTB[2],oTB[3]);
                *(float4*)(soutV + tid * SROW + g*4)          = make_float4(oVA[0],oVA[1],oVA[2],oVA[3]);
                *(float4*)(soutV + (tid+NTHR) * SROW + g*4)   = make_float4(oVB[0],oVB[1],oVB[2],oVB[3]);
            }
            __syncwarp();                  // sout writes visible to all lanes
            // coalesced flush of staged outputs
            const int h0 = (tile - FTILES) * TILE;
            #pragma unroll
            for (int it = 0; it < 12; it++) {
                int q = tid + it * NTHR;
                int r = q / CHK, j = q - r * CHK;
                size_t o = (size_t)(row0 + r) * HFCST + h0 + j * 4;
                *(float4*)(out + o) = *(const float4*)(soutT + r * SROW + j * 4);
                *(float4*)(out + (size_t)B * HFCST + o) = *(const float4*)(soutV + r * SROW + j * 4);
            }
            __syncwarp();                  // flush reads done before sout reuse
        }
    }
}

extern "C" void kernel_launch(void* const* d_in, const int* in_sizes, int n_in,
                              void* d_out, int out_size) {
    const float* T_obs = (const float*)d_in[0];
    const float* T_air = (const float*)d_in[1];
    const float* wind  = (const float*)d_in[2];
    const float* par   = (const float*)d_in[3];
    const float* dtv   = (const float*)d_in[4];
    // d_in[5] = L_hist (compile-time constant 336)
    const float* k_raw  = (const float*)d_in[6];
    const float* log_q  = (const float*)d_in[7];
    const float* log_r  = (const float*)d_in[8];
    const float* log_p0 = (const float*)d_in[9];
    const float* log_qs = (const float*)d_in[10];
    const float* tpl = (const float*)d_in[11];
    const float* tpq = (const float*)d_in[12];
    const float* twc = (const float*)d_in[13];
    const float* ts_ = (const float*)d_in[14];
    const float* tfc = (const float*)d_in[15];

    int B = in_sizes[0] / TTOT;
    cudaFuncSetAttribute(kf_kernel, cudaFuncAttributeMaxDynamicSharedMemorySize, SMEM_BYTES);
    int blocks = B / RPB;
    kf_kernel<<<blocks, NTHR, SMEM_BYTES>>>(T_obs, T_air, wind, par, dtv,
                                            k_raw, log_q, log_r, log_p0, log_qs,
                                            tpl, tpq, twc, ts_, tfc,
                                            (float*)d_out, B);
}

// round 11
// speedup vs baseline: 1.1648x; 1.1648x over previous
#include <cuda_runtime.h>

// Batched Kalman filter + forecast. B=16384 rows, T=504 (336 filter + 168 fcst).
// R2 skeleton (the empirical best): 256 blocks x 64 threads, one row/thread,
// 24-step tiles, conflict-free smem (SROW=28). PIPE=3 with
// cp.async.wait_group 1 -> TWO tiles in flight during compute (R2 had one and
// a full drain per tile). Final tile uses wait_group 0 (only its own group is
// pending there; wait_group 1 would NOT wait -> race, fixed this round).
// Forecast output staging overlays the dead T_obs slots of stages 0/1
// (forecast tiles skip T_obs loads).
// P_update = (1-K)^2*Pp + K^2*R == K*R exactly (K = Pp/S, 1-K = R/S).

#define TTOT   504
#define LHIST  336
#define HFCST  168
#define TILE   24
#define NTILES 21     // 504/24
#define FTILES 14     // 336/24
#define RPB    64     // rows per block == threads per block
#define SROW   28     // smem floats per row (24 data + 4 pad; 7 x 16B groups)
#define SARR   (RPB*SROW)              // 1792 floats per array per stage
#define PIPE   3
#define CHK    6                       // 16B chunks per row per tile
#define SIN_FLOATS  (PIPE*5*SARR)      // 26880
#define SMEM_BYTES  (SIN_FLOATS*4)     // 107520 B -> 2 blocks/SM

#define EL(v,i) ((i)==0?(v).x:((i)==1?(v).y:((i)==2?(v).z:(v).w)))

__global__ __launch_bounds__(RPB)
void kf_kernel(const float* __restrict__ T_obs,
               const float* __restrict__ T_air,
               const float* __restrict__ wind,
               const float* __restrict__ par,
               const float* __restrict__ dtv,
               const float* __restrict__ k_raw_p,
               const float* __restrict__ log_q_p,
               const float* __restrict__ log_r_p,
               const float* __restrict__ log_p0_p,
               const float* __restrict__ log_qs_p,
               const float* __restrict__ tpl_p,
               const float* __restrict__ tpq_p,
               const float* __restrict__ twc_p,
               const float* __restrict__ ts_p,
               const float* __restrict__ tfc_p,
               float* __restrict__ out,
               int B)
{
    extern __shared__ float smem[];
    float* sin   = smem;                      // [PIPE][5][SARR]
    float* soutT = sin + (0*5 + 0)*SARR;      // overlay: stage0 T_obs slot
    float* soutV = sin + (1*5 + 0)*SARR;      // overlay: stage1 T_obs slot

    const int tid  = threadIdx.x;
    const int row0 = blockIdx.x * RPB;

    const float* arrs[5] = {T_obs, T_air, wind, par, dtv};

    // cooperative coalesced tile loader; a0=1 skips T_obs (forecast tiles)
    auto issue_tile = [&](int tile, int buf, int a0) {
        for (int a = a0; a < 5; a++) {
            const float* gb = arrs[a];
            #pragma unroll
            for (int it = 0; it < CHK; it++) {
                int q = tid + it * RPB;            // 0..383
                int r = q / CHK, j = q - r * CHK;  // row, 16B chunk
                const float* g = gb + (size_t)(row0 + r) * TTOT + tile * TILE + j * 4;
                float* ds = sin + (buf * 5 + a) * SARR + r * SROW + j * 4;
                unsigned du = (unsigned)__cvta_generic_to_shared(ds);
                asm volatile("cp.async.cg.shared.global [%0], [%1], 16;\n" :: "r"(du), "l"(g));
            }
        }
        asm volatile("cp.async.commit_group;\n");
    };

    // prologue: two tiles in flight before any wait; scalar math overlaps
    issue_tile(0, 0, 0);
    issue_tile(1, 1, 0);

    const float k   = log1pf(expf(__ldg(k_raw_p)));
    const float qq  = expf(__ldg(log_qs_p)) * expf(__ldg(log_q_p));
    const float R   = expf(__ldg(log_r_p));
    const float P0  = expf(__ldg(log_p0_p));
    const float tpl = __ldg(tpl_p);
    const float tpq = __ldg(tpq_p);
    const float twc = __ldg(twc_p);
    const float ts  = __ldg(ts_p);
    const float tfc = __ldg(tfc_p);

    float s = 0.0f, P = P0;
    float pTa = 0.0f, pw = 0.0f, pp = 0.0f;

    for (int tile = 0; tile < NTILES; ++tile) {
        const int buf = tile % PIPE;
        // Pending groups here: {tile, tile+1} (except last tile: {tile} only).
        // Drain so that THIS tile's group is complete:
        if (tile == NTILES - 1) {
            asm volatile("cp.async.wait_group 0;\n" ::: "memory");
        } else {
            asm volatile("cp.async.wait_group 1;\n" ::: "memory");
        }
        __syncthreads();   // data visible; buf (tile+2)%PIPE == (tile-1)%PIPE free

        // keep two tiles in flight through the compute below
        if (tile + 2 < NTILES)
            issue_tile(tile + 2, (tile + 2) % PIPE, (tile + 2 >= FTILES) ? 1 : 0);

        const float* by  = sin + (buf * 5 + 0) * SARR + tid * SROW;
        const float* bta = by  + SARR;
        const float* bw  = bta + SARR;
        const float* bp  = bw  + SARR;
        const float* bd  = bp  + SARR;

        if (tile < FTILES) {
            // ---------------- filter phase ----------------
            #pragma unroll
            for (int g = 0; g < CHK; g++) {
                float4 y4 = *(const float4*)(by  + g * 4);
                float4 t4 = *(const float4*)(bta + g * 4);
                float4 w4 = *(const float4*)(bw  + g * 4);
                float4 p4 = *(const float4*)(bp  + g * 4);
                float4 d4 = *(const float4*)(bd  + g * 4);
                #pragma unroll
                for (int i = 0; i < 4; i++) {
                    float yv = EL(y4,i), tav = EL(t4,i), wv = EL(w4,i),
                          pv = EL(p4,i), dv = EL(d4,i);
                    if (!(tile == 0 && g == 0 && i == 0)) {
                        float dtt = fmaxf(dv, 1.0f);
                        float dT  = s - pTa;
                        float cl  = tpl * pp + tpq * pp * pp + twc * pw
                                  + ts * dT + tfc * pw * dT;
                        float Tp  = s + (cl - k * dT) * dtt;
                        Tp = fminf(fmaxf(Tp, -50.0f), 100.0f);
                        float F = 1.0f + ((ts + tfc * pw) - k) * dtt;
                        F = fminf(fmaxf(F, -2.0f), 2.0f);
                        float Pp = F * F * P + qq * dtt;
                        Pp = fminf(fmaxf(Pp, 1e-10f), 1e6f);
                        float K = __fdividef(Pp, Pp + R);
                        s = Tp + K * (yv - Tp);
                        P = K * R;
                    } else {
                        s = yv;
                    }
                    pTa = tav; pw = wv; pp = pv;
                }
            }
            // buffer reuse is ordered by the top-of-loop __syncthreads
        } else {
            // ---------------- forecast phase ----------------
            #pragma unroll
            for (int g = 0; g < CHK; g++) {
                float4 t4 = *(const float4*)(bta + g * 4);
                float4 w4 = *(const float4*)(bw  + g * 4);
                float4 p4 = *(const float4*)(bp  + g * 4);
                float4 d4 = *(const float4*)(bd  + g * 4);
                float oT[4], oV[4];
                #pragma unroll
                for (int i = 0; i < 4; i++) {
                    float tav = EL(t4,i), wv = EL(w4,i), pv = EL(p4,i), dv = EL(d4,i);
                    float dtt = fmaxf(dv, 1.0f);
                    float dT  = s - pTa;
                    float cl  = tpl * pp + tpq * pp * pp + twc * pw
                              + ts * dT + tfc * pw * dT;
                    float Tp  = s + (cl - k * dT) * dtt;
                    Tp = fminf(fmaxf(Tp, -50.0f), 100.0f);
                    float F = 1.0f + ((ts + tfc * pw) - k) * dtt;
                    F = fminf(fmaxf(F, -2.0f), 2.0f);
                    float Pp = F * F * P + qq * dtt;
                    Pp = fminf(fmaxf(Pp, 1e-10f), 1e6f);
                    s = Tp; P = Pp;
                    oT[i] = Tp; oV[i] = Pp;
                    pTa = tav; pw = wv; pp = pv;
                }
                *(float4*)(soutT + tid * SROW + g * 4) = make_float4(oT[0], oT[1], oT[2], oT[3]);
                *(float4*)(soutV + tid * SROW + g * 4) = make_float4(oV[0], oV[1], oV[2], oV[3]);
            }
            __syncthreads();                   // staged outputs visible
            const int h0 = (tile - FTILES) * TILE;
            #pragma unroll
            for (int it = 0; it < CHK; it++) {
                int q = tid + it * RPB;
                int r = q / CHK, j = q - r * CHK;
                size_t o = (size_t)(row0 + r) * HFCST + h0 + j * 4;
                *(float4*)(out + o) = *(const float4*)(soutT + r * SROW + j * 4);
                *(float4*)(out + (size_t)B * HFCST + o) = *(const float4*)(soutV + r * SROW + j * 4);
            }
            // next iteration's top __syncthreads orders sout reuse
        }
    }
}

extern "C" void kernel_launch(void* const* d_in, const int* in_sizes, int n_in,
                              void* d_out, int out_size) {
    const float* T_obs = (const float*)d_in[0];
    const float* T_air = (const float*)d_in[1];
    const float* wind  = (const float*)d_in[2];
    const float* par   = (const float*)d_in[3];
    const float* dtv   = (const float*)d_in[4];
    // d_in[5] = L_hist (compile-time constant 336)
    const float* k_raw  = (const float*)d_in[6];
    const float* log_q  = (const float*)d_in[7];
    const float* log_r  = (const float*)d_in[8];
    const float* log_p0 = (const float*)d_in[9];
    const float* log_qs = (const float*)d_in[10];
    const float* tpl = (const float*)d_in[11];
    const float* tpq = (const float*)d_in[12];
    const float* twc = (const float*)d_in[13];
    const float* ts_ = (const float*)d_in[14];
    const float* tfc = (const float*)d_in[15];

    int B = in_sizes[0] / TTOT;
    cudaFuncSetAttribute(kf_kernel, cudaFuncAttributeMaxDynamicSharedMemorySize, SMEM_BYTES);
    int blocks = B / RPB;
    kf_kernel<<<blocks, RPB, SMEM_BYTES>>>(T_obs, T_air, wind, par, dtv,
                                           k_raw, log_q, log_r, log_p0, log_qs,
                                           tpl, tpq, twc, ts_, tfc,
                                           (float*)d_out, B);
}

// round 12
// speedup vs baseline: 1.4012x; 1.2029x over previous
#include <cuda_runtime.h>

// Batched Kalman filter + forecast. B=16384 rows, T=504 (336 filter + 168 fcst).
// R2 skeleton: 256 blocks x 64 threads, one row/thread, 24-step tiles,
// conflict-free smem (SROW=28). PIPE=3, cp.async.wait_group 1 -> two tiles in
// flight during compute (final tile: wait_group 0). Loader is COMPILE-TIME
// specialized (template<SKIP_Y>, named pointers, fully unrolled, shared
// address math) — the runtime-a0 loader of R6-R11 spilled the pointer array
// to local memory and serialized the cp.async issue stream.
// P_update = (1-K)^2*Pp + K^2*R == K*R exactly (K = Pp/S, 1-K = R/S).

#define TTOT   504
#define LHIST  336
#define HFCST  168
#define TILE   24
#define NTILES 21     // 504/24
#define FTILES 14     // 336/24
#define RPB    64     // rows per block == threads per block
#define SROW   28     // smem floats per row (24 data + 4 pad; 7 x 16B groups)
#define SARR   (RPB*SROW)              // 1792 floats per array per stage
#define PIPE   3
#define CHK    6                       // 16B chunks per row per tile
#define SIN_FLOATS  (PIPE*5*SARR)      // 26880
#define SMEM_BYTES  (SIN_FLOATS*4)     // 107520 B -> 2 blocks/SM

#define EL(v,i) ((i)==0?(v).x:((i)==1?(v).y:((i)==2?(v).z:(v).w)))

__device__ __forceinline__ void cp16(float* ds, const float* g) {
    unsigned du = (unsigned)__cvta_generic_to_shared(ds);
    asm volatile("cp.async.cg.shared.global [%0], [%1], 16;\n" :: "r"(du), "l"(g));
}

template<bool SKIP_Y>
__device__ __forceinline__ void issue_tile(const float* __restrict__ T_obs,
                                           const float* __restrict__ T_air,
                                           const float* __restrict__ wind,
                                           const float* __restrict__ par,
                                           const float* __restrict__ dtv,
                                           float* sbuf, int row0, int tile, int tid)
{
    #pragma unroll
    for (int it = 0; it < CHK; it++) {
        int q = tid + it * RPB;                 // 0..383
        int r = q / CHK, j = q - r * CHK;       // row, 16B chunk
        size_t go = (size_t)(row0 + r) * TTOT + tile * TILE + j * 4;
        int so = r * SROW + j * 4;
        if (!SKIP_Y) cp16(sbuf + 0*SARR + so, T_obs + go);
        cp16(sbuf + 1*SARR + so, T_air + go);
        cp16(sbuf + 2*SARR + so, wind + go);
        cp16(sbuf + 3*SARR + so, par  + go);
        cp16(sbuf + 4*SARR + so, dtv  + go);
    }
    asm volatile("cp.async.commit_group;\n");
}

__global__ __launch_bounds__(RPB)
void kf_kernel(const float* __restrict__ T_obs,
               const float* __restrict__ T_air,
               const float* __restrict__ wind,
               const float* __restrict__ par,
               const float* __restrict__ dtv,
               const float* __restrict__ k_raw_p,
               const float* __restrict__ log_q_p,
               const float* __restrict__ log_r_p,
               const float* __restrict__ log_p0_p,
               const float* __restrict__ log_qs_p,
               const float* __restrict__ tpl_p,
               const float* __restrict__ tpq_p,
               const float* __restrict__ twc_p,
               const float* __restrict__ ts_p,
               const float* __restrict__ tfc_p,
               float* __restrict__ out,
               int B)
{
    extern __shared__ float smem[];
    float* sin   = smem;                      // [PIPE][5][SARR]
    float* soutT = sin + (0*5 + 0)*SARR;      // overlay: stage0 T_obs slot
    float* soutV = sin + (1*5 + 0)*SARR;      // overlay: stage1 T_obs slot

    const int tid  = threadIdx.x;
    const int row0 = blockIdx.x * RPB;

    // prologue: two tiles in flight before any wait; scalar math overlaps
    issue_tile<false>(T_obs, T_air, wind, par, dtv, sin + 0*5*SARR, row0, 0, tid);
    issue_tile<false>(T_obs, T_air, wind, par, dtv, sin + 1*5*SARR, row0, 1, tid);

    const float k   = log1pf(expf(__ldg(k_raw_p)));
    const float qq  = expf(__ldg(log_qs_p)) * expf(__ldg(log_q_p));
    const float R   = expf(__ldg(log_r_p));
    const float P0  = expf(__ldg(log_p0_p));
    const float tpl = __ldg(tpl_p);
    const float tpq = __ldg(tpq_p);
    const float twc = __ldg(twc_p);
    const float ts  = __ldg(ts_p);
    const float tfc = __ldg(tfc_p);

    float s = 0.0f, P = P0;
    float pTa = 0.0f, pw = 0.0f, pp = 0.0f;

    for (int tile = 0; tile < NTILES; ++tile) {
        const int buf = tile % PIPE;
        // Pending groups: {tile, tile+1} (last tile: {tile} only) -> drain tile's group
        if (tile == NTILES - 1) {
            asm volatile("cp.async.wait_group 0;\n" ::: "memory");
        } else {
            asm volatile("cp.async.wait_group 1;\n" ::: "memory");
        }
        __syncthreads();   // data visible; buf (tile+2)%PIPE == (tile-1)%PIPE free

        // keep two tiles in flight through the compute below
        if (tile + 2 < NTILES) {
            float* nb = sin + ((tile + 2) % PIPE) * 5 * SARR;
            if (tile + 2 >= FTILES)
                issue_tile<true >(T_obs, T_air, wind, par, dtv, nb, row0, tile + 2, tid);
            else
                issue_tile<false>(T_obs, T_air, wind, par, dtv, nb, row0, tile + 2, tid);
        }

        const float* by  = sin + (buf * 5 + 0) * SARR + tid * SROW;
        const float* bta = by  + SARR;
        const float* bw  = bta + SARR;
        const float* bp  = bw  + SARR;
        const float* bd  = bp  + SARR;

        if (tile < FTILES) {
            // ---------------- filter phase ----------------
            #pragma unroll
            for (int g = 0; g < CHK; g++) {
                float4 y4 = *(const float4*)(by  + g * 4);
                float4 t4 = *(const float4*)(bta + g * 4);
                float4 w4 = *(const float4*)(bw  + g * 4);
                float4 p4 = *(const float4*)(bp  + g * 4);
                float4 d4 = *(const float4*)(bd  + g * 4);
                #pragma unroll
                for (int i = 0; i < 4; i++) {
                    float yv = EL(y4,i), tav = EL(t4,i), wv = EL(w4,i),
                          pv = EL(p4,i), dv = EL(d4,i);
                    if (!(tile == 0 && g == 0 && i == 0)) {
                        float dtt = fmaxf(dv, 1.0f);
                        float dT  = s - pTa;
                        float cl  = tpl * pp + tpq * pp * pp + twc * pw
                                  + ts * dT + tfc * pw * dT;
                        float Tp  = s + (cl - k * dT) * dtt;
                        Tp = fminf(fmaxf(Tp, -50.0f), 100.0f);
                        float F = 1.0f + ((ts + tfc * pw) - k) * dtt;
                        F = fminf(fmaxf(F, -2.0f), 2.0f);
                        float Pp = F * F * P + qq * dtt;
                        Pp = fminf(fmaxf(Pp, 1e-10f), 1e6f);
                        float K = __fdividef(Pp, Pp + R);
                        s = Tp + K * (yv - Tp);
                        P = K * R;
                    } else {
                        s = yv;
                    }
                    pTa = tav; pw = wv; pp = pv;
                }
            }
            // buffer reuse is ordered by the top-of-loop __syncthreads
        } else {
            // ---------------- forecast phase ----------------
            #pragma unroll
            for (int g = 0; g < CHK; g++) {
                float4 t4 = *(const float4*)(bta + g * 4);
                float4 w4 = *(const float4*)(bw  + g * 4);
                float4 p4 = *(const float4*)(bp  + g * 4);
                float4 d4 = *(const float4*)(bd  + g * 4);
                float oT[4], oV[4];
                #pragma unroll
                for (int i = 0; i < 4; i++) {
                    float tav = EL(t4,i), wv = EL(w4,i), pv = EL(p4,i), dv = EL(d4,i);
                    float dtt = fmaxf(dv, 1.0f);
                    float dT  = s - pTa;
                    float cl  = tpl * pp + tpq * pp * pp + twc * pw
                              + ts * dT + tfc * pw * dT;
                    float Tp  = s + (cl - k * dT) * dtt;
                    Tp = fminf(fmaxf(Tp, -50.0f), 100.0f);
                    float F = 1.0f + ((ts + tfc * pw) - k) * dtt;
                    F = fminf(fmaxf(F, -2.0f), 2.0f);
                    float Pp = F * F * P + qq * dtt;
                    Pp = fminf(fmaxf(Pp, 1e-10f), 1e6f);
                    s = Tp; P = Pp;
                    oT[i] = Tp; oV[i] = Pp;
                    pTa = tav; pw = wv; pp = pv;
                }
                *(float4*)(soutT + tid * SROW + g * 4) = make_float4(oT[0], oT[1], oT[2], oT[3]);
                *(float4*)(soutV + tid * SROW + g * 4) = make_float4(oV[0], oV[1], oV[2], oV[3]);
            }
            __syncthreads();                   // staged outputs visible
            const int h0 = (tile - FTILES) * TILE;
            #pragma unroll
            for (int it = 0; it < CHK; it++) {
                int q = tid + it * RPB;
                int r = q / CHK, j = q - r * CHK;
                size_t o = (size_t)(row0 + r) * HFCST + h0 + j * 4;
                *(float4*)(out + o) = *(const float4*)(soutT + r * SROW + j * 4);
                *(float4*)(out + (size_t)B * HFCST + o) = *(const float4*)(soutV + r * SROW + j * 4);
            }
            // next iteration's top __syncthreads orders sout reuse
        }
    }
}

extern "C" void kernel_launch(void* const* d_in, const int* in_sizes, int n_in,
                              void* d_out, int out_size) {
    const float* T_obs = (const float*)d_in[0];
    const float* T_air = (const float*)d_in[1];
    const float* wind  = (const float*)d_in[2];
    const float* par   = (const float*)d_in[3];
    const float* dtv   = (const float*)d_in[4];
    // d_in[5] = L_hist (compile-time constant 336)
    const float* k_raw  = (const float*)d_in[6];
    const float* log_q  = (const float*)d_in[7];
    const float* log_r  = (const float*)d_in[8];
    const float* log_p0 = (const float*)d_in[9];
    const float* log_qs = (const float*)d_in[10];
    const float* tpl = (const float*)d_in[11];
    const float* tpq = (const float*)d_in[12];
    const float* twc = (const float*)d_in[13];
    const float* ts_ = (const float*)d_in[14];
    const float* tfc = (const float*)d_in[15];

    int B = in_sizes[0] / TTOT;
    cudaFuncSetAttribute(kf_kernel, cudaFuncAttributeMaxDynamicSharedMemorySize, SMEM_BYTES);
    int blocks = B / RPB;
    kf_kernel<<<blocks, RPB, SMEM_BYTES>>>(T_obs, T_air, wind, par, dtv,
                                           k_raw, log_q, log_r, log_p0, log_qs,
                                           tpl, tpq, twc, ts_, tfc,
                                           (float*)d_out, B);
}